// round 7
// baseline (speedup 1.0000x reference)
#include <cuda_runtime.h>
#include <cuda_bf16.h>
#include <cuda_fp16.h>
#include <cstdint>

// SimpleGraphSAGE on GB300 (sm_103a harness; baseline-PTX only — no tcgen05).
// Identity: mean_nbr(x) @ W_bot == mean_nbr(x @ W_bot).
// Layer L: Yself[N,64](fp32) | Ynbr[N,64](fp16) = A @ [W_top | W_bot]
//   layer1: A = x
//   layer2: A = relu(Yself1 + b1 + mean_nbr(Ynbr1))   <- gather FUSED into staging
// final:   out = Yself2 + b2 + mean_nbr(Ynbr2)
// Graph: dst = repeat(arange(N),16) -> node i's neighbors are src[16i..16i+15].

#define NN    100000
#define DEG   16
#define F     64
#define MTILE 128

// Static device scratch (no allocations allowed). Double-buffered Y (layer2's
// staging reads layer1's Y for random neighbors while other CTAs write -> must
// not alias).
__device__ __align__(128) float  g_Yself_a[(size_t)NN * F];
__device__ __align__(128) __half g_Ynbr_a [(size_t)NN * F];
__device__ __align__(128) float  g_Yself_b[(size_t)NN * F];
__device__ __align__(128) __half g_Ynbr_b [(size_t)NN * F];
// Fragment-ready split weights: [layer][(ks*16+nt)*32 + lane] -> uint4{bh0,bh1,bl0,bl1}
__device__ __align__(128) uint4  g_Bf[2][2048];

#define MMA_BF16(c, a0, a1, a2, a3, b0, b1)                               \
    asm volatile(                                                          \
        "mma.sync.aligned.m16n8k16.row.col.f32.bf16.bf16.f32 "            \
        "{%0,%1,%2,%3}, {%4,%5,%6,%7}, {%8,%9}, {%0,%1,%2,%3};"           \
        : "+f"((c)[0]), "+f"((c)[1]), "+f"((c)[2]), "+f"((c)[3])          \
        : "r"(a0), "r"(a1), "r"(a2), "r"(a3), "r"(b0), "r"(b1))

__device__ __forceinline__ void split_pack(float x0, float x1,
                                           uint32_t& hi, uint32_t& lo) {
    __nv_bfloat162 h = __floats2bfloat162_rn(x0, x1);
    float r0 = x0 - __low2float(h), r1 = x1 - __high2float(h);
    __nv_bfloat162 l = __floats2bfloat162_rn(r0, r1);
    hi = *reinterpret_cast<uint32_t*>(&h);
    lo = *reinterpret_cast<uint32_t*>(&l);
}

// ---- One-shot: fragment-ready split weights for both layers ----
// Wcat[k][n] = n<64 ? W[k*64+n] : W[(64+k)*64+(n-64)] ; word kw = (k=2kw, 2kw+1)
// mma frag: lane l, step ks, tile nt: col = nt*8 + (l>>2); kw0 = ks*8+(l&3), kw1 = kw0+4.
__global__ void prep_w(const float* __restrict__ W1, const float* __restrict__ W2)
{
    const int id    = blockIdx.x * 256 + threadIdx.x;   // 4096 total
    const int layer = id >> 11;
    const int slot  = id & 2047;                         // (ks*16+nt)*32 + l
    const int l     = slot & 31;
    const int nt    = (slot >> 5) & 15;
    const int ks    = slot >> 9;
    const float* W  = layer ? W2 : W1;
    const int col   = nt * 8 + (l >> 2);
    uint32_t hiw[2], low[2];
    #pragma unroll
    for (int j = 0; j < 2; j++) {
        const int kw = ks * 8 + (l & 3) + j * 4;
        const int k0 = 2 * kw, k1 = k0 + 1;
        float x0, x1;
        if (col < 64) { x0 = W[k0 * 64 + col];               x1 = W[k1 * 64 + col]; }
        else          { x0 = W[(64 + k0) * 64 + (col - 64)]; x1 = W[(64 + k1) * 64 + (col - 64)]; }
        split_pack(x0, x1, hiw[j], low[j]);
    }
    g_Bf[layer][slot] = make_uint4(hiw[0], hiw[1], low[0], low[1]);
}

// ---- smem (u32 words): A hi [128*36] + A lo [128*36] = 36864 B ----
#define ASTR 36
#define SMEM_WORDS (2 * 128 * ASTR)

// FUSED=0: A = Xself (x rows).  FUSED=1: A = relu(Xself + bias_in + mean Xnbr[src]).
template <int FUSED>
__global__ void __launch_bounds__(256, 2) sage_gemm_t(
    const float* __restrict__ Xself, const __half* __restrict__ Xnbr,
    const float* __restrict__ bias_in, const int* __restrict__ src,
    const uint4* __restrict__ Bf,
    float* __restrict__ Yself, __half* __restrict__ Ynbr)
{
    extern __shared__ uint32_t sm[];
    uint32_t* sAh = sm;
    uint32_t* sAl = sm + 128 * ASTR;

    const int tid  = threadIdx.x;
    const int base = blockIdx.x * MTILE;

    // ---- Stage A: 2 threads per row; each handles 32 features ----
    {
        const int row  = tid >> 1;
        const int half = tid & 1;
        const int node = base + row;
        float v[32];
        if (node < NN) {
            if (!FUSED) {
                const float4* p = (const float4*)(Xself + (size_t)node * F + half * 32);
                #pragma unroll
                for (int i = 0; i < 8; i++) {
                    float4 q = p[i];
                    v[4*i+0] = q.x; v[4*i+1] = q.y; v[4*i+2] = q.z; v[4*i+3] = q.w;
                }
            } else {
                // fused gather: mean of 16 neighbor rows (fp16, half2 accumulation)
                const int4* sp4 = (const int4*)(src + (size_t)node * DEG);
                int4 i0 = sp4[0], i1 = sp4[1], i2 = sp4[2], i3 = sp4[3];
                int sid[16] = { i0.x, i0.y, i0.z, i0.w, i1.x, i1.y, i1.z, i1.w,
                                i2.x, i2.y, i2.z, i2.w, i3.x, i3.y, i3.z, i3.w };
                __half2 hacc[16];
                #pragma unroll
                for (int j = 0; j < 16; j++) hacc[j] = __float2half2_rn(0.f);
                #pragma unroll
                for (int e = 0; e < DEG; e++) {
                    const uint4* np = (const uint4*)(Xnbr + (size_t)sid[e] * F + half * 32);
                    uint4 q0 = np[0], q1 = np[1], q2 = np[2], q3 = np[3];
                    const __half2* h0 = (const __half2*)&q0;
                    const __half2* h1 = (const __half2*)&q1;
                    const __half2* h2 = (const __half2*)&q2;
                    const __half2* h3 = (const __half2*)&q3;
                    #pragma unroll
                    for (int j = 0; j < 4; j++) {
                        hacc[j]      = __hadd2(hacc[j],      h0[j]);
                        hacc[4 + j]  = __hadd2(hacc[4 + j],  h1[j]);
                        hacc[8 + j]  = __hadd2(hacc[8 + j],  h2[j]);
                        hacc[12 + j] = __hadd2(hacc[12 + j], h3[j]);
                    }
                }
                const float  inv = 1.0f / (float)DEG;
                const float4* p  = (const float4*)(Xself   + (size_t)node * F + half * 32);
                const float4* bp = (const float4*)(bias_in + half * 32);
                #pragma unroll
                for (int i = 0; i < 8; i++) {
                    float4 s = p[i], b = bp[i];
                    float2 m0 = __half22float2(hacc[2*i]);
                    float2 m1 = __half22float2(hacc[2*i+1]);
                    v[4*i+0] = fmaxf(s.x + b.x + m0.x * inv, 0.f);
                    v[4*i+1] = fmaxf(s.y + b.y + m0.y * inv, 0.f);
                    v[4*i+2] = fmaxf(s.z + b.z + m1.x * inv, 0.f);
                    v[4*i+3] = fmaxf(s.w + b.w + m1.y * inv, 0.f);
                }
            }
        } else {
            #pragma unroll
            for (int i = 0; i < 32; i++) v[i] = 0.0f;
        }
        uint32_t* dh = sAh + row * ASTR + half * 16;
        uint32_t* dl = sAl + row * ASTR + half * 16;
        #pragma unroll
        for (int j = 0; j < 16; j++) {
            uint32_t hw, lw;
            split_pack(v[2*j], v[2*j+1], hw, lw);
            dh[j] = hw; dl[j] = lw;
        }
    }
    __syncthreads();

    // ---- Warp MMA: warp w -> rows [w*16,+16) x 128 cols; B via L1-hot LDG.128 ----
    const int warp = tid >> 5, l = tid & 31;
    const int arow = warp * 16 + (l >> 2);
    const int lk   = l & 3;

    float c[16][4];
    #pragma unroll
    for (int nt = 0; nt < 16; nt++) {
        c[nt][0] = 0.f; c[nt][1] = 0.f; c[nt][2] = 0.f; c[nt][3] = 0.f;
    }

    #pragma unroll
    for (int ks = 0; ks < 4; ks++) {
        const int kb = ks * 8;
        uint32_t ah0 = sAh[ arow      * ASTR + kb + lk];
        uint32_t ah1 = sAh[(arow + 8) * ASTR + kb + lk];
        uint32_t ah2 = sAh[ arow      * ASTR + kb + lk + 4];
        uint32_t ah3 = sAh[(arow + 8) * ASTR + kb + lk + 4];
        uint32_t al0 = sAl[ arow      * ASTR + kb + lk];
        uint32_t al1 = sAl[(arow + 8) * ASTR + kb + lk];
        uint32_t al2 = sAl[ arow      * ASTR + kb + lk + 4];
        uint32_t al3 = sAl[(arow + 8) * ASTR + kb + lk + 4];

        #pragma unroll
        for (int nt = 0; nt < 16; nt++) {
            uint4 b = __ldg(&Bf[(ks * 16 + nt) * 32 + l]);  // {bh0,bh1,bl0,bl1}
            MMA_BF16(c[nt], ah0, ah1, ah2, ah3, b.x, b.y);
            MMA_BF16(c[nt], ah0, ah1, ah2, ah3, b.z, b.w);
            MMA_BF16(c[nt], al0, al1, al2, al3, b.x, b.y);
        }
    }

    // ---- Epilogue: cols 0..63 -> Yself fp32, cols 64..127 -> Ynbr fp16 ----
    const int r0 = base + arow;
    const int r1 = r0 + 8;
    #pragma unroll
    for (int nt = 0; nt < 8; nt++) {
        const int col = nt * 8 + lk * 2;
        if (r0 < NN) *(float2*)(Yself + (size_t)r0 * F + col) = make_float2(c[nt][0], c[nt][1]);
        if (r1 < NN) *(float2*)(Yself + (size_t)r1 * F + col) = make_float2(c[nt][2], c[nt][3]);
    }
    #pragma unroll
    for (int nt = 8; nt < 16; nt++) {
        const int col = (nt - 8) * 8 + lk * 2;
        if (r0 < NN) *(__half2*)(Ynbr + (size_t)r0 * F + col) = __floats2half2_rn(c[nt][0], c[nt][1]);
        if (r1 < NN) *(__half2*)(Ynbr + (size_t)r1 * F + col) = __floats2half2_rn(c[nt][2], c[nt][3]);
    }
}

// out[i] = Yself[i] + b + (1/16) * sum_e Ynbr[src[16i+e]]   (no relu on final layer)
// 8 threads per node (16B of fp16 each); every gather LDG.128 covers full lines.
__global__ void __launch_bounds__(256) sage_gather(
    const float* __restrict__ Yself, const __half* __restrict__ Ynbr,
    const float* __restrict__ bias, const int* __restrict__ src,
    float* __restrict__ out)
{
    const int tid  = threadIdx.x;
    const int lane = tid & 31;
    const int nq   = lane >> 3;          // node within warp quad (0..3)
    const int t8   = lane & 7;           // 16B chunk (8 fp16) within row
    const int node = (blockIdx.x * 256 + tid) >> 3;   // exact grid, no tail

    const int2 sp = *(const int2*)(src + (size_t)node * DEG + t8 * 2);

    float acc[8];
    #pragma unroll
    for (int j = 0; j < 8; j++) acc[j] = 0.f;

    #pragma unroll
    for (int e = 0; e < DEG; e++) {
        int s = __shfl_sync(0xffffffffu, (e & 1) ? sp.y : sp.x, (nq << 3) + (e >> 1));
        uint4 v = *(const uint4*)(Ynbr + (size_t)s * F + t8 * 8);
        float2 f0 = __half22float2(*(__half2*)&v.x);
        float2 f1 = __half22float2(*(__half2*)&v.y);
        float2 f2 = __half22float2(*(__half2*)&v.z);
        float2 f3 = __half22float2(*(__half2*)&v.w);
        acc[0] += f0.x; acc[1] += f0.y; acc[2] += f1.x; acc[3] += f1.y;
        acc[4] += f2.x; acc[5] += f2.y; acc[6] += f3.x; acc[7] += f3.y;
    }

    const float inv = 1.0f / (float)DEG;
    const float* selfp = Yself + (size_t)node * F + t8 * 8;
    float4 sa = *(const float4*)(selfp);
    float4 sb = *(const float4*)(selfp + 4);
    float4 ba = *(const float4*)(bias + t8 * 8);
    float4 bb = *(const float4*)(bias + t8 * 8 + 4);

    float4 r0, r1;
    r0.x = sa.x + ba.x + acc[0] * inv;
    r0.y = sa.y + ba.y + acc[1] * inv;
    r0.z = sa.z + ba.z + acc[2] * inv;
    r0.w = sa.w + ba.w + acc[3] * inv;
    r1.x = sb.x + bb.x + acc[4] * inv;
    r1.y = sb.y + bb.y + acc[5] * inv;
    r1.z = sb.z + bb.z + acc[6] * inv;
    r1.w = sb.w + bb.w + acc[7] * inv;

    float* op = out + (size_t)node * F + t8 * 8;
    *(float4*)(op)     = r0;
    *(float4*)(op + 4) = r1;
}

extern "C" void kernel_launch(void* const* d_in, const int* in_sizes, int n_in,
                              void* d_out, int out_size)
{
    const float* x   = (const float*)d_in[0];
    const float* W1  = (const float*)d_in[1];
    const float* b1  = (const float*)d_in[2];
    const float* W2  = (const float*)d_in[3];
    const float* b2  = (const float*)d_in[4];
    const int*   src = (const int*)  d_in[5];
    float* out = (float*)d_out;

    void* p = nullptr;
    cudaGetSymbolAddress(&p, g_Yself_a);  float*  Ysa = (float*)p;
    cudaGetSymbolAddress(&p, g_Ynbr_a);   __half* Yna = (__half*)p;
    cudaGetSymbolAddress(&p, g_Yself_b);  float*  Ysb = (float*)p;
    cudaGetSymbolAddress(&p, g_Ynbr_b);   __half* Ynb = (__half*)p;
    cudaGetSymbolAddress(&p, g_Bf);       uint4*  Bf  = (uint4*)p;

    const size_t smem = SMEM_WORDS * sizeof(uint32_t);  // 36864 B
    cudaFuncSetAttribute(sage_gemm_t<0>, cudaFuncAttributeMaxDynamicSharedMemorySize, (int)smem);
    cudaFuncSetAttribute(sage_gemm_t<1>, cudaFuncAttributeMaxDynamicSharedMemorySize, (int)smem);

    const int gemm_grid   = (NN + MTILE - 1) / MTILE;   // 782
    const int gather_grid = NN / 32;                     // 3125 (exact: 32 nodes/block)

    prep_w<<<16, 256>>>(W1, W2);
    sage_gemm_t<0><<<gemm_grid, 256, smem>>>(x,   nullptr, nullptr, nullptr, Bf,        Ysa, Yna);
    sage_gemm_t<1><<<gemm_grid, 256, smem>>>(Ysa, Yna,     b1,      src,     Bf + 2048, Ysb, Ynb);
    sage_gather  <<<gather_grid, 256>>>(Ysb, Ynb, b2, src, out);
}

// round 8
// speedup vs baseline: 1.0989x; 1.0989x over previous
#include <cuda_runtime.h>
#include <cuda_bf16.h>
#include <cuda_fp16.h>
#include <cstdint>

// SimpleGraphSAGE on GB300 (sm_103a harness; baseline-PTX only — no tcgen05).
// Identity: mean_nbr(x) @ W_bot == mean_nbr(x @ W_bot).
// Per layer: Yself[N,64](fp32) | Ynbr[N,64](fp16) = X[N,64] @ [W_top | W_bot]
//            h[i] = act(Yself[i] + b + (1/16) * sum_e Ynbr[src[16i+e]])
// Graph: dst = repeat(arange(N),16) -> node i's neighbors are src[16i..16i+15].

#define NN    100000
#define DEG   16
#define F     64
#define MTILE 128

// Static device scratch (no allocations allowed).
__device__ __align__(128) float  g_Yself[(size_t)NN * F];
__device__ __align__(128) __half g_Ynbr [(size_t)NN * F];
__device__ __align__(128) float  g_h    [(size_t)NN * F];
// Fragment-ready split weights: [layer][(ks*16+nt)*32 + lane] -> uint4{bh0,bh1,bl0,bl1}
__device__ __align__(128) uint4  g_Bf[2][2048];

#define MMA_BF16(c, a0, a1, a2, a3, b0, b1)                               \
    asm volatile(                                                          \
        "mma.sync.aligned.m16n8k16.row.col.f32.bf16.bf16.f32 "            \
        "{%0,%1,%2,%3}, {%4,%5,%6,%7}, {%8,%9}, {%0,%1,%2,%3};"           \
        : "+f"((c)[0]), "+f"((c)[1]), "+f"((c)[2]), "+f"((c)[3])          \
        : "r"(a0), "r"(a1), "r"(a2), "r"(a3), "r"(b0), "r"(b1))

__device__ __forceinline__ void split_pack(float x0, float x1,
                                           uint32_t& hi, uint32_t& lo) {
    __nv_bfloat162 h = __floats2bfloat162_rn(x0, x1);
    float r0 = x0 - __low2float(h), r1 = x1 - __high2float(h);
    __nv_bfloat162 l = __floats2bfloat162_rn(r0, r1);
    hi = *reinterpret_cast<uint32_t*>(&h);
    lo = *reinterpret_cast<uint32_t*>(&l);
}

// ---- One-shot: fragment-ready split weights for both layers ----
// Wcat[k][n] = n<64 ? W[k*64+n] : W[(64+k)*64+(n-64)] ; word kw = (k=2kw, 2kw+1)
// mma frag: lane l, step ks, tile nt: col = nt*8 + (l>>2); kw0 = ks*8+(l&3), kw1 = kw0+4.
__global__ void prep_w(const float* __restrict__ W1, const float* __restrict__ W2)
{
    const int id    = blockIdx.x * 256 + threadIdx.x;   // 4096 total
    const int layer = id >> 11;
    const int slot  = id & 2047;                         // (ks*16+nt)*32 + l
    const int l     = slot & 31;
    const int nt    = (slot >> 5) & 15;
    const int ks    = slot >> 9;
    const float* W  = layer ? W2 : W1;
    const int col   = nt * 8 + (l >> 2);
    uint32_t hiw[2], low[2];
    #pragma unroll
    for (int j = 0; j < 2; j++) {
        const int kw = ks * 8 + (l & 3) + j * 4;
        const int k0 = 2 * kw, k1 = k0 + 1;
        float x0, x1;
        if (col < 64) { x0 = W[k0 * 64 + col];               x1 = W[k1 * 64 + col]; }
        else          { x0 = W[(64 + k0) * 64 + (col - 64)]; x1 = W[(64 + k1) * 64 + (col - 64)]; }
        split_pack(x0, x1, hiw[j], low[j]);
    }
    g_Bf[layer][slot] = make_uint4(hiw[0], hiw[1], low[0], low[1]);
}

// ---- smem (u32 words): A hi [128*36] + A lo [128*36] = 36864 B ----
#define ASTR 36
#define SMEM_WORDS (2 * 128 * ASTR)

// GEMM: Y[tile,0:64]=Yself fp32, Y[tile,64:128]=Ynbr fp16.
// N split into two passes of 8 n-tiles each -> 32 accum regs live at a time.
__global__ void __launch_bounds__(256, 3) sage_gemm(
    const float* __restrict__ X, const uint4* __restrict__ Bf,
    float* __restrict__ Yself, __half* __restrict__ Ynbr)
{
    extern __shared__ uint32_t sm[];
    uint32_t* sAh = sm;
    uint32_t* sAl = sm + 128 * ASTR;

    const int tid  = threadIdx.x;
    const int base = blockIdx.x * MTILE;

    // ---- Stage A: 2 threads per row; each converts 32 features to bf16 hi/lo ----
    {
        const int row  = tid >> 1;
        const int half = tid & 1;
        const int node = base + row;
        float v[32];
        if (node < NN) {
            const float4* p = (const float4*)(X + (size_t)node * F + half * 32);
            #pragma unroll
            for (int i = 0; i < 8; i++) {
                float4 q = p[i];
                v[4*i+0] = q.x; v[4*i+1] = q.y; v[4*i+2] = q.z; v[4*i+3] = q.w;
            }
        } else {
            #pragma unroll
            for (int i = 0; i < 32; i++) v[i] = 0.0f;
        }
        uint32_t* dh = sAh + row * ASTR + half * 16;
        uint32_t* dl = sAl + row * ASTR + half * 16;
        #pragma unroll
        for (int j = 0; j < 16; j++) {
            uint32_t hw, lw;
            split_pack(v[2*j], v[2*j+1], hw, lw);
            dh[j] = hw; dl[j] = lw;
        }
    }
    __syncthreads();

    const int warp = tid >> 5, l = tid & 31;
    const int arow = warp * 16 + (l >> 2);
    const int lk   = l & 3;
    const int r0   = base + arow;
    const int r1   = r0 + 8;

    // ---- Pass 0: n-tiles 0..7 (cols 0..63) -> Yself fp32 ----
    {
        float c[8][4];
        #pragma unroll
        for (int nt = 0; nt < 8; nt++) { c[nt][0]=0.f; c[nt][1]=0.f; c[nt][2]=0.f; c[nt][3]=0.f; }

        #pragma unroll
        for (int ks = 0; ks < 4; ks++) {
            const int kb = ks * 8;
            uint32_t ah0 = sAh[ arow      * ASTR + kb + lk];
            uint32_t ah1 = sAh[(arow + 8) * ASTR + kb + lk];
            uint32_t ah2 = sAh[ arow      * ASTR + kb + lk + 4];
            uint32_t ah3 = sAh[(arow + 8) * ASTR + kb + lk + 4];
            uint32_t al0 = sAl[ arow      * ASTR + kb + lk];
            uint32_t al1 = sAl[(arow + 8) * ASTR + kb + lk];
            uint32_t al2 = sAl[ arow      * ASTR + kb + lk + 4];
            uint32_t al3 = sAl[(arow + 8) * ASTR + kb + lk + 4];
            #pragma unroll
            for (int nt = 0; nt < 8; nt++) {
                uint4 b = __ldg(&Bf[(ks * 16 + nt) * 32 + l]);  // {bh0,bh1,bl0,bl1}
                MMA_BF16(c[nt], ah0, ah1, ah2, ah3, b.x, b.y);
                MMA_BF16(c[nt], ah0, ah1, ah2, ah3, b.z, b.w);
                MMA_BF16(c[nt], al0, al1, al2, al3, b.x, b.y);
            }
        }
        #pragma unroll
        for (int nt = 0; nt < 8; nt++) {
            const int col = nt * 8 + lk * 2;
            if (r0 < NN) *(float2*)(Yself + (size_t)r0 * F + col) = make_float2(c[nt][0], c[nt][1]);
            if (r1 < NN) *(float2*)(Yself + (size_t)r1 * F + col) = make_float2(c[nt][2], c[nt][3]);
        }
    }

    // ---- Pass 1: n-tiles 8..15 (cols 64..127) -> Ynbr fp16 ----
    {
        float c[8][4];
        #pragma unroll
        for (int nt = 0; nt < 8; nt++) { c[nt][0]=0.f; c[nt][1]=0.f; c[nt][2]=0.f; c[nt][3]=0.f; }

        #pragma unroll
        for (int ks = 0; ks < 4; ks++) {
            const int kb = ks * 8;
            uint32_t ah0 = sAh[ arow      * ASTR + kb + lk];
            uint32_t ah1 = sAh[(arow + 8) * ASTR + kb + lk];
            uint32_t ah2 = sAh[ arow      * ASTR + kb + lk + 4];
            uint32_t ah3 = sAh[(arow + 8) * ASTR + kb + lk + 4];
            uint32_t al0 = sAl[ arow      * ASTR + kb + lk];
            uint32_t al1 = sAl[(arow + 8) * ASTR + kb + lk];
            uint32_t al2 = sAl[ arow      * ASTR + kb + lk + 4];
            uint32_t al3 = sAl[(arow + 8) * ASTR + kb + lk + 4];
            #pragma unroll
            for (int nt = 0; nt < 8; nt++) {
                uint4 b = __ldg(&Bf[(ks * 16 + nt + 8) * 32 + l]);
                MMA_BF16(c[nt], ah0, ah1, ah2, ah3, b.x, b.y);
                MMA_BF16(c[nt], ah0, ah1, ah2, ah3, b.z, b.w);
                MMA_BF16(c[nt], al0, al1, al2, al3, b.x, b.y);
            }
        }
        #pragma unroll
        for (int nt = 0; nt < 8; nt++) {
            const int col = nt * 8 + lk * 2;
            if (r0 < NN) *(__half2*)(Ynbr + (size_t)r0 * F + col) = __floats2half2_rn(c[nt][0], c[nt][1]);
            if (r1 < NN) *(__half2*)(Ynbr + (size_t)r1 * F + col) = __floats2half2_rn(c[nt][2], c[nt][3]);
        }
    }
}

// out[i] = act( Yself[i] + b + (1/16) * sum_e Ynbr[src[16i+e]] )
// 8 threads per node (16B of fp16 each); every gather LDG.128 covers full lines.
__global__ void __launch_bounds__(256) sage_gather(
    const float* __restrict__ Yself, const __half* __restrict__ Ynbr,
    const float* __restrict__ bias, const int* __restrict__ src,
    float* __restrict__ out, int do_relu)
{
    const int tid  = threadIdx.x;
    const int lane = tid & 31;
    const int nq   = lane >> 3;          // node within warp quad (0..3)
    const int t8   = lane & 7;           // 16B chunk (8 fp16) within row
    const int node = (blockIdx.x * 256 + tid) >> 3;   // exact grid, no tail

    const int2 sp = *(const int2*)(src + (size_t)node * DEG + t8 * 2);

    float acc[8];
    #pragma unroll
    for (int j = 0; j < 8; j++) acc[j] = 0.f;

    #pragma unroll
    for (int e = 0; e < DEG; e++) {
        int s = __shfl_sync(0xffffffffu, (e & 1) ? sp.y : sp.x, (nq << 3) + (e >> 1));
        uint4 v = *(const uint4*)(Ynbr + (size_t)s * F + t8 * 8);
        float2 f0 = __half22float2(*(__half2*)&v.x);
        float2 f1 = __half22float2(*(__half2*)&v.y);
        float2 f2 = __half22float2(*(__half2*)&v.z);
        float2 f3 = __half22float2(*(__half2*)&v.w);
        acc[0] += f0.x; acc[1] += f0.y; acc[2] += f1.x; acc[3] += f1.y;
        acc[4] += f2.x; acc[5] += f2.y; acc[6] += f3.x; acc[7] += f3.y;
    }

    const float inv = 1.0f / (float)DEG;
    const float* selfp = Yself + (size_t)node * F + t8 * 8;
    float4 sa = *(const float4*)(selfp);
    float4 sb = *(const float4*)(selfp + 4);
    float4 ba = *(const float4*)(bias + t8 * 8);
    float4 bb = *(const float4*)(bias + t8 * 8 + 4);

    float r[8];
    r[0] = sa.x + ba.x + acc[0] * inv;
    r[1] = sa.y + ba.y + acc[1] * inv;
    r[2] = sa.z + ba.z + acc[2] * inv;
    r[3] = sa.w + ba.w + acc[3] * inv;
    r[4] = sb.x + bb.x + acc[4] * inv;
    r[5] = sb.y + bb.y + acc[5] * inv;
    r[6] = sb.z + bb.z + acc[6] * inv;
    r[7] = sb.w + bb.w + acc[7] * inv;
    if (do_relu) {
        #pragma unroll
        for (int j = 0; j < 8; j++) r[j] = fmaxf(r[j], 0.f);
    }
    float* op = out + (size_t)node * F + t8 * 8;
    *(float4*)(op)     = make_float4(r[0], r[1], r[2], r[3]);
    *(float4*)(op + 4) = make_float4(r[4], r[5], r[6], r[7]);
}

extern "C" void kernel_launch(void* const* d_in, const int* in_sizes, int n_in,
                              void* d_out, int out_size)
{
    const float* x   = (const float*)d_in[0];
    const float* W1  = (const float*)d_in[1];
    const float* b1  = (const float*)d_in[2];
    const float* W2  = (const float*)d_in[3];
    const float* b2  = (const float*)d_in[4];
    const int*   src = (const int*)  d_in[5];
    float* out = (float*)d_out;

    void* p = nullptr;
    cudaGetSymbolAddress(&p, g_Yself);  float*  Yself = (float*)p;
    cudaGetSymbolAddress(&p, g_Ynbr);   __half* Ynbr  = (__half*)p;
    cudaGetSymbolAddress(&p, g_h);      float*  h     = (float*)p;
    cudaGetSymbolAddress(&p, g_Bf);     uint4*  Bf    = (uint4*)p;

    const size_t smem = SMEM_WORDS * sizeof(uint32_t);  // 36864 B
    cudaFuncSetAttribute(sage_gemm, cudaFuncAttributeMaxDynamicSharedMemorySize, (int)smem);

    const int gemm_grid   = (NN + MTILE - 1) / MTILE;   // 782
    const int gather_grid = NN / 32;                     // 3125 (exact: 32 nodes/block)

    prep_w<<<16, 256>>>(W1, W2);
    sage_gemm  <<<gemm_grid, 256, smem>>>(x, Bf,        Yself, Ynbr);
    sage_gather<<<gather_grid, 256>>>(Yself, Ynbr, b1, src, h, 1);
    sage_gemm  <<<gemm_grid, 256, smem>>>(h, Bf + 2048, Yself, Ynbr);
    sage_gather<<<gather_grid, 256>>>(Yself, Ynbr, b2, src, out, 0);
}